// round 12
// baseline (speedup 1.0000x reference)
#include <cuda_runtime.h>
#include <cuda_bf16.h>
#include <math.h>

// Problem constants (fixed by the dataset)
#define MAXN 100000
#define MAXE 1600000
#define F 32            // F_IN == F_OUT == 32
#define SCAN_B 256      // elements per scan block

// Scratch (static device globals; no allocation allowed)
__device__ int   d_idx64;            // 1 if edge_index is int64, 0 if int32
__device__ float d_deg[MAXN];        // degree -> dinv (after k_scan3)
__device__ int   d_cnt[MAXN];        // counts -> exclusive prefix (cursor) -> inclusive
__device__ int   d_bsum[1024];       // per-block sums for the scan
__device__ int   d_src[MAXE];        // int32 source indices (unsorted)
__device__ int   d_dst[MAXE];        // int32 dest indices (unsorted)
__device__ float d_w[MAXE];          // weight, zeroed for self loops / bad edges
__device__ int2  d_edge[MAXE];       // CSR-by-dst: {src, coef bits}

// ---------------------------------------------------------------------------
// f32x2 packed-pipe helpers (sm_103a dual-fp32)
// ---------------------------------------------------------------------------
__device__ __forceinline__ unsigned long long pk2(float lo, float hi) {
    unsigned long long r;
    asm("mov.b64 %0, {%1, %2};" : "=l"(r) : "f"(lo), "f"(hi));
    return r;
}
__device__ __forceinline__ void upk2(unsigned long long v, float& lo, float& hi) {
    asm("mov.b64 {%0, %1}, %2;" : "=f"(lo), "=f"(hi) : "l"(v));
}
__device__ __forceinline__ unsigned long long fma2(unsigned long long a,
                                                   unsigned long long b,
                                                   unsigned long long c) {
    unsigned long long d;
    asm("fma.rn.f32x2 %0, %1, %2, %3;" : "=l"(d) : "l"(a), "l"(b), "l"(c));
    return d;
}

// ---------------------------------------------------------------------------
// K0: zero deg/cnt; block 0, warp 0 additionally detects edge_index dtype.
// ---------------------------------------------------------------------------
__global__ void k_init(const void* __restrict__ ei, int E, int n) {
    int i = blockIdx.x * blockDim.x + threadIdx.x;
    if (i < n) { d_deg[i] = 0.0f; d_cnt[i] = 0; }
    if (blockIdx.x == 0 && threadIdx.x < 32) {
        const long long* p = (const long long*)ei;
        int lane = threadIdx.x;
        long long a = p[lane];
        long long b = p[E + lane];
        int bad = (a < 0 || a >= n || b < 0 || b >= n) ? 1 : 0;
        unsigned m = __ballot_sync(0xffffffffu, bad);
        if (lane == 0) d_idx64 = (m == 0u) ? 1 : 0;
    }
}

// ---------------------------------------------------------------------------
// K1: vectorized pass over edge_index (2 edges/thread):
//   - convert indices to int32 scratch
//   - zero self-loop / OOB weights
//   - deg[src] += w  and  cnt[dst] += 1
// ---------------------------------------------------------------------------
__global__ void k_prep(const void* __restrict__ ei,
                       const float* __restrict__ ew, int E, int n) {
    int t = blockIdx.x * blockDim.x + threadIdx.x;
    int e0 = t * 2;
    if (e0 >= E) return;
    int s0, s1, d0, d1;
    float w0, w1;
    bool pair = (e0 + 1 < E);
    if (pair) {
        if (d_idx64) {
            const long long* b = (const long long*)ei;
            longlong2 sv = ((const longlong2*)b)[t];
            longlong2 dv = ((const longlong2*)(b + E))[t];
            s0 = (int)sv.x; s1 = (int)sv.y;
            d0 = (int)dv.x; d1 = (int)dv.y;
        } else {
            const int* b = (const int*)ei;
            int2 sv = ((const int2*)b)[t];
            int2 dv = ((const int2*)(b + E))[t];
            s0 = sv.x; s1 = sv.y; d0 = dv.x; d1 = dv.y;
        }
        float2 wv = ((const float2*)ew)[t];
        w0 = wv.x; w1 = wv.y;
    } else {
        if (d_idx64) {
            const long long* b = (const long long*)ei;
            s0 = (int)b[e0]; d0 = (int)b[E + e0];
        } else {
            const int* b = (const int*)ei;
            s0 = b[e0]; d0 = b[E + e0];
        }
        w0 = ew[e0];
        s1 = 0; d1 = 0; w1 = 0.0f;
    }
    if ((unsigned)s0 >= (unsigned)n || (unsigned)d0 >= (unsigned)n) { s0 = 0; d0 = 0; w0 = 0.0f; }
    if ((unsigned)s1 >= (unsigned)n || (unsigned)d1 >= (unsigned)n) { s1 = 0; d1 = 0; w1 = 0.0f; }
    if (s0 == d0) w0 = 0.0f;
    if (s1 == d1) w1 = 0.0f;
    if (pair) {
        ((int2*)d_src)[t]   = make_int2(s0, s1);
        ((int2*)d_dst)[t]   = make_int2(d0, d1);
        ((float2*)d_w)[t]   = make_float2(w0, w1);
    } else {
        d_src[e0] = s0; d_dst[e0] = d0; d_w[e0] = w0;
    }
    if (w0 != 0.0f) { atomicAdd(&d_deg[s0], w0); atomicAdd(&d_cnt[d0], 1); }
    if (w1 != 0.0f) { atomicAdd(&d_deg[s1], w1); atomicAdd(&d_cnt[d1], 1); }
}

// ---------------------------------------------------------------------------
// K2a: per-block sums of cnt
// ---------------------------------------------------------------------------
__global__ void k_scan1(int n) {
    __shared__ int wsum[SCAN_B / 32];
    int t = threadIdx.x;
    int i = blockIdx.x * SCAN_B + t;
    int v = (i < n) ? d_cnt[i] : 0;
#pragma unroll
    for (int off = 16; off > 0; off >>= 1)
        v += __shfl_down_sync(0xffffffffu, v, off);
    if ((t & 31) == 0) wsum[t >> 5] = v;
    __syncthreads();
    if (t == 0) {
        int s = 0;
#pragma unroll
        for (int j = 0; j < SCAN_B / 32; j++) s += wsum[j];
        d_bsum[blockIdx.x] = s;
    }
}

// ---------------------------------------------------------------------------
// K2b: one block, exclusive scan of per-block sums (nb <= 1024)
// ---------------------------------------------------------------------------
__global__ void k_scan2(int nb) {
    __shared__ int sv[1024];
    int t = threadIdx.x;
    int v = (t < nb) ? d_bsum[t] : 0;
    sv[t] = v;
    __syncthreads();
    for (int off = 1; off < 1024; off <<= 1) {
        int u = (t >= off) ? sv[t - off] : 0;
        __syncthreads();
        sv[t] += u;
        __syncthreads();
    }
    if (t < nb) d_bsum[t] = sv[t] - v;   // exclusive
}

// ---------------------------------------------------------------------------
// K2c: per-block exclusive scan + base -> cursor; deg -> dinv (fused)
// ---------------------------------------------------------------------------
__global__ void k_scan3(int n) {
    __shared__ int wsum[SCAN_B / 32];
    int t = threadIdx.x;
    int lane = t & 31, w = t >> 5;
    int i = blockIdx.x * SCAN_B + t;
    int v = (i < n) ? d_cnt[i] : 0;
    int s = v;
#pragma unroll
    for (int off = 1; off < 32; off <<= 1) {
        int u = __shfl_up_sync(0xffffffffu, s, off);
        if (lane >= off) s += u;
    }
    if (lane == 31) wsum[w] = s;
    __syncthreads();
    if (t == 0) {
        int run = 0;
#pragma unroll
        for (int j = 0; j < SCAN_B / 32; j++) {
            int c = wsum[j]; wsum[j] = run; run += c;
        }
    }
    __syncthreads();
    if (i < n) {
        d_cnt[i] = (s - v) + wsum[w] + d_bsum[blockIdx.x];
        float dg = d_deg[i];
        d_deg[i] = (dg > 0.0f) ? rsqrtf(dg) : 0.0f;
    }
}

// ---------------------------------------------------------------------------
// K3: reorder edges into CSR-by-dst as int2 {src, coefbits} (one STG.64).
//     coef = -dinv[src] * w * dinv[dst]   (d_deg holds dinv)
// ---------------------------------------------------------------------------
__global__ void k_reorder(int E) {
    int e = blockIdx.x * blockDim.x + threadIdx.x;
    if (e >= E) return;
    float w = d_w[e];
    if (w == 0.0f) return;
    int s = d_src[e];
    int d = d_dst[e];
    float c = -d_deg[s] * w * d_deg[d];
    int pos = atomicAdd(&d_cnt[d], 1);
    d_edge[pos] = make_int2(s, __float_as_int(c));
}

// ---------------------------------------------------------------------------
// K4: fused gather (tx1 in registers) + gates + output.
// One warp handles 4 nodes; lane = output feature. Gather inner loop is
// unrolled x8 with zero-padded lanes (8 independent LDGs in flight).
// Gate matvecs use fma.rn.f32x2 (2 nodes per instruction); weights in
// static smem (24 KB -> high residency for latency-bound gather).
// ---------------------------------------------------------------------------
__global__ void __launch_bounds__(256)
k_gather_gates(const float* __restrict__ x,
               const float* __restrict__ Wx,
               const float* __restrict__ bx,
               const float* __restrict__ bh,
               const float* __restrict__ wc,
               const float* __restrict__ bgate,
               const float* __restrict__ linw,
               const float* __restrict__ linb,
               float* __restrict__ out, int n) {
    __shared__ float sW[6][F * F];   // Wi0, Wi1, Wc0, Wc1, Wo0, Wo1
    __shared__ float sBi[F], sBc[F], sBo[F], sWc2[F], sLw[F];
    __shared__ float sLb;

    int tid = threadIdx.x;
    for (int i = tid; i < F * F; i += blockDim.x) {
        sW[0][i] = Wx[0 * F * F + i];   // gate i, k=0
        sW[1][i] = Wx[1 * F * F + i];   // gate i, k=1
        sW[2][i] = Wx[4 * F * F + i];   // gate c, k=0
        sW[3][i] = Wx[5 * F * F + i];   // gate c, k=1
        sW[4][i] = Wx[6 * F * F + i];   // gate o, k=0
        sW[5][i] = Wx[7 * F * F + i];   // gate o, k=1
    }
    if (tid < F) {
        sBi[tid]  = bx[0 * F + tid] + bh[0 * F + tid] + bgate[0 * F + tid];
        sBc[tid]  = bx[2 * F + tid] + bh[2 * F + tid] + bgate[2 * F + tid];
        sBo[tid]  = bx[3 * F + tid] + bh[3 * F + tid] + bgate[3 * F + tid];
        sWc2[tid] = wc[2 * F + tid];
        sLw[tid]  = linw[tid];
        if (tid == 0) sLb = linb[0];
    }
    __syncthreads();

    int warp = tid >> 5;
    int lane = tid & 31;
    int base = (blockIdx.x * (blockDim.x >> 5) + warp) * 4;
    if (base >= n) return;

    // -------- gather phase: x row + tx1 for 4 nodes into registers --------
    float xr[4], tr[4];
#pragma unroll
    for (int i = 0; i < 4; i++) {
        int nd = base + i;
        float acc = 0.0f, xv = 0.0f;
        if (nd < n) {                       // warp-uniform condition
            xv = x[nd * F + lane];
            int st = nd ? d_cnt[nd - 1] : 0;
            int en = d_cnt[nd];
            for (int b0 = st; b0 < en; b0 += 32) {
                int j = b0 + lane;
                int sj = 0, cb = 0;
                if (j < en) { int2 ed = d_edge[j]; sj = ed.x; cb = ed.y; }
                int mm = (min(32, en - b0) + 7) & ~7;
                for (int k = 0; k < mm; k += 8) {
                    int   s0 = __shfl_sync(0xffffffffu, sj, k);
                    int   s1 = __shfl_sync(0xffffffffu, sj, k + 1);
                    int   s2 = __shfl_sync(0xffffffffu, sj, k + 2);
                    int   s3 = __shfl_sync(0xffffffffu, sj, k + 3);
                    int   s4 = __shfl_sync(0xffffffffu, sj, k + 4);
                    int   s5 = __shfl_sync(0xffffffffu, sj, k + 5);
                    int   s6 = __shfl_sync(0xffffffffu, sj, k + 6);
                    int   s7 = __shfl_sync(0xffffffffu, sj, k + 7);
                    float c0 = __int_as_float(__shfl_sync(0xffffffffu, cb, k));
                    float c1 = __int_as_float(__shfl_sync(0xffffffffu, cb, k + 1));
                    float c2 = __int_as_float(__shfl_sync(0xffffffffu, cb, k + 2));
                    float c3 = __int_as_float(__shfl_sync(0xffffffffu, cb, k + 3));
                    float c4 = __int_as_float(__shfl_sync(0xffffffffu, cb, k + 4));
                    float c5 = __int_as_float(__shfl_sync(0xffffffffu, cb, k + 5));
                    float c6 = __int_as_float(__shfl_sync(0xffffffffu, cb, k + 6));
                    float c7 = __int_as_float(__shfl_sync(0xffffffffu, cb, k + 7));
                    float v0 = __ldg(&x[s0 * F + lane]);
                    float v1 = __ldg(&x[s1 * F + lane]);
                    float v2 = __ldg(&x[s2 * F + lane]);
                    float v3 = __ldg(&x[s3 * F + lane]);
                    float v4 = __ldg(&x[s4 * F + lane]);
                    float v5 = __ldg(&x[s5 * F + lane]);
                    float v6 = __ldg(&x[s6 * F + lane]);
                    float v7 = __ldg(&x[s7 * F + lane]);
                    acc += c0 * v0 + c1 * v1 + c2 * v2 + c3 * v3
                         + c4 * v4 + c5 * v5 + c6 * v6 + c7 * v7;
                }
            }
        }
        xr[i] = xv;
        tr[i] = acc;
    }

    // -------- gate phase: packed f32x2, 2 nodes per instruction --------
    float bi = sBi[lane], bc = sBc[lane], bo = sBo[lane];
    unsigned long long ai01 = pk2(bi, bi), ai23 = pk2(bi, bi);
    unsigned long long ac01 = pk2(bc, bc), ac23 = pk2(bc, bc);
    unsigned long long ao01 = pk2(bo, bo), ao23 = pk2(bo, bo);

#pragma unroll
    for (int f = 0; f < F; f++) {
        float w0 = sW[0][f * F + lane];
        float w1 = sW[1][f * F + lane];
        float w2 = sW[2][f * F + lane];
        float w3 = sW[3][f * F + lane];
        float w4 = sW[4][f * F + lane];
        float w5 = sW[5][f * F + lane];
        float xf0 = __shfl_sync(0xffffffffu, xr[0], f);
        float xf1 = __shfl_sync(0xffffffffu, xr[1], f);
        float xf2 = __shfl_sync(0xffffffffu, xr[2], f);
        float xf3 = __shfl_sync(0xffffffffu, xr[3], f);
        float tf0 = __shfl_sync(0xffffffffu, tr[0], f);
        float tf1 = __shfl_sync(0xffffffffu, tr[1], f);
        float tf2 = __shfl_sync(0xffffffffu, tr[2], f);
        float tf3 = __shfl_sync(0xffffffffu, tr[3], f);
        unsigned long long x01 = pk2(xf0, xf1), x23 = pk2(xf2, xf3);
        unsigned long long t01 = pk2(tf0, tf1), t23 = pk2(tf2, tf3);
        unsigned long long W0 = pk2(w0, w0), W1 = pk2(w1, w1);
        unsigned long long W2 = pk2(w2, w2), W3 = pk2(w3, w3);
        unsigned long long W4 = pk2(w4, w4), W5 = pk2(w5, w5);
        ai01 = fma2(x01, W0, fma2(t01, W1, ai01));
        ai23 = fma2(x23, W0, fma2(t23, W1, ai23));
        ac01 = fma2(x01, W2, fma2(t01, W3, ac01));
        ac23 = fma2(x23, W2, fma2(t23, W3, ac23));
        ao01 = fma2(x01, W4, fma2(t01, W5, ao01));
        ao23 = fma2(x23, W4, fma2(t23, W5, ao23));
    }

    float ai[4], ac[4], ao[4];
    upk2(ai01, ai[0], ai[1]); upk2(ai23, ai[2], ai[3]);
    upk2(ac01, ac[0], ac[1]); upk2(ac23, ac[2], ac[3]);
    upk2(ao01, ao[0], ao[1]); upk2(ao23, ao[2], ao[3]);

    float wcl = sWc2[lane], lwl = sLw[lane], lb = sLb;
#pragma unroll
    for (int i = 0; i < 4; i++) {
        int nd = base + i;
        if (nd >= n) break;                  // warp-uniform
        float I = 1.0f / (1.0f + __expf(-ai[i]));
        float T = tanhf(ac[i]);
        float C = I * T;
        float O = 1.0f / (1.0f + __expf(-(ao[i] + wcl * C)));
        float H = O * tanhf(C);
        float r = fmaxf(H, 0.0f) * lwl;
#pragma unroll
        for (int off = 16; off > 0; off >>= 1)
            r += __shfl_xor_sync(0xffffffffu, r, off);
        if (lane == 0) out[nd] = r + lb;
    }
}

// ---------------------------------------------------------------------------
extern "C" void kernel_launch(void* const* d_in, const int* in_sizes, int n_in,
                              void* d_out, int out_size) {
    const float* x     = (const float*)d_in[0];
    const void*  ei    = d_in[1];
    const float* ew    = (const float*)d_in[2];
    const float* Wx    = (const float*)d_in[3];
    const float* bx    = (const float*)d_in[4];
    // d_in[5] = Wh (dead: H_prev == 0)
    const float* bh    = (const float*)d_in[6];
    const float* wc    = (const float*)d_in[7];
    const float* bgate = (const float*)d_in[8];
    const float* linw  = (const float*)d_in[9];
    const float* linb  = (const float*)d_in[10];
    float*       out   = (float*)d_out;

    const int N = in_sizes[0] / F;
    const int E = in_sizes[2];

    const int B  = 256;
    const int NB = (N + SCAN_B - 1) / SCAN_B;   // scan blocks (<=1024)

    k_init<<<(N + B - 1) / B, B>>>(ei, E, N);
    k_prep<<<((E + 1) / 2 + B - 1) / B, B>>>(ei, ew, E, N);
    k_scan1<<<NB, SCAN_B>>>(N);
    k_scan2<<<1, 1024>>>(NB);
    k_scan3<<<NB, SCAN_B>>>(N);
    k_reorder<<<(E + B - 1) / B, B>>>(E);
    // 8 warps/block, 4 nodes/warp -> 32 nodes per block
    k_gather_gates<<<(N + 31) / 32, B>>>(x, Wx, bx, bh, wc, bgate, linw, linb,
                                         out, N);
}

// round 13
// speedup vs baseline: 1.4610x; 1.4610x over previous
#include <cuda_runtime.h>
#include <cuda_bf16.h>
#include <math.h>

// Problem constants (fixed by the dataset)
#define MAXN 100000
#define MAXE 1600000
#define F 32            // F_IN == F_OUT == 32
#define SCAN_B 256      // elements per scan block

// Scratch (static device globals; no allocation allowed)
__device__ int   d_idx64;            // 1 if edge_index is int64, 0 if int32
__device__ float d_deg[MAXN];        // degree -> dinv (after k_scan3)
__device__ int   d_cnt[MAXN];        // counts -> exclusive prefix (cursor) -> inclusive
__device__ int   d_bsum[1024];       // per-block sums for the scan
__device__ int   d_src[MAXE];        // int32 source indices (unsorted)
__device__ int   d_dst[MAXE];        // int32 dest indices (unsorted)
__device__ float d_w[MAXE];          // weight, zeroed for self loops / bad edges
__device__ int   d_esrc[MAXE];       // src sorted by dst (CSR)
__device__ float d_ecoef[MAXE];      // coef sorted by dst (CSR)

// ---------------------------------------------------------------------------
// f32x2 packed-pipe helpers (sm_103a dual-fp32)
// ---------------------------------------------------------------------------
__device__ __forceinline__ unsigned long long pk2(float lo, float hi) {
    unsigned long long r;
    asm("mov.b64 %0, {%1, %2};" : "=l"(r) : "f"(lo), "f"(hi));
    return r;
}
__device__ __forceinline__ void upk2(unsigned long long v, float& lo, float& hi) {
    asm("mov.b64 {%0, %1}, %2;" : "=f"(lo), "=f"(hi) : "l"(v));
}
__device__ __forceinline__ unsigned long long fma2(unsigned long long a,
                                                   unsigned long long b,
                                                   unsigned long long c) {
    unsigned long long d;
    asm("fma.rn.f32x2 %0, %1, %2, %3;" : "=l"(d) : "l"(a), "l"(b), "l"(c));
    return d;
}

// ---------------------------------------------------------------------------
// K0: zero deg/cnt; block 0, warp 0 additionally detects edge_index dtype.
// ---------------------------------------------------------------------------
__global__ void k_init(const void* __restrict__ ei, int E, int n) {
    int i = blockIdx.x * blockDim.x + threadIdx.x;
    if (i < n) { d_deg[i] = 0.0f; d_cnt[i] = 0; }
    if (blockIdx.x == 0 && threadIdx.x < 32) {
        const long long* p = (const long long*)ei;
        int lane = threadIdx.x;
        long long a = p[lane];
        long long b = p[E + lane];
        int bad = (a < 0 || a >= n || b < 0 || b >= n) ? 1 : 0;
        unsigned m = __ballot_sync(0xffffffffu, bad);
        if (lane == 0) d_idx64 = (m == 0u) ? 1 : 0;
    }
}

// ---------------------------------------------------------------------------
// K1: single pass over edge_index:
//   - convert indices to int32 scratch
//   - zero self-loop / OOB weights
//   - deg[src] += w  and  cnt[dst] += 1 (skip dead edges entirely)
// ---------------------------------------------------------------------------
__global__ void k_prep(const void* __restrict__ ei,
                       const float* __restrict__ ew, int E, int n) {
    int e = blockIdx.x * blockDim.x + threadIdx.x;
    if (e >= E) return;
    int s, d;
    if (d_idx64) {
        const long long* p = (const long long*)ei;
        s = (int)p[e];
        d = (int)p[E + e];
    } else {
        const int* p = (const int*)ei;
        s = p[e];
        d = p[E + e];
    }
    float w = ew[e];
    if ((unsigned)s >= (unsigned)n || (unsigned)d >= (unsigned)n) {
        s = 0; d = 0; w = 0.0f;
    }
    if (s == d) w = 0.0f;
    d_src[e] = s;
    d_dst[e] = d;
    d_w[e]   = w;
    if (w != 0.0f) {
        atomicAdd(&d_deg[s], w);
        atomicAdd(&d_cnt[d], 1);
    }
}

// ---------------------------------------------------------------------------
// K2a: per-block sums of cnt (SCAN_B elements per block, coalesced)
// ---------------------------------------------------------------------------
__global__ void k_scan1(int n) {
    __shared__ int wsum[SCAN_B / 32];
    int t = threadIdx.x;
    int i = blockIdx.x * SCAN_B + t;
    int v = (i < n) ? d_cnt[i] : 0;
#pragma unroll
    for (int off = 16; off > 0; off >>= 1)
        v += __shfl_down_sync(0xffffffffu, v, off);
    if ((t & 31) == 0) wsum[t >> 5] = v;
    __syncthreads();
    if (t == 0) {
        int s = 0;
#pragma unroll
        for (int j = 0; j < SCAN_B / 32; j++) s += wsum[j];
        d_bsum[blockIdx.x] = s;
    }
}

// ---------------------------------------------------------------------------
// K2b: one block, exclusive scan of per-block sums (nb <= 1024)
// ---------------------------------------------------------------------------
__global__ void k_scan2(int nb) {
    __shared__ int sv[1024];
    int t = threadIdx.x;
    int v = (t < nb) ? d_bsum[t] : 0;
    sv[t] = v;
    __syncthreads();
    for (int off = 1; off < 1024; off <<= 1) {
        int u = (t >= off) ? sv[t - off] : 0;
        __syncthreads();
        sv[t] += u;
        __syncthreads();
    }
    if (t < nb) d_bsum[t] = sv[t] - v;   // exclusive
}

// ---------------------------------------------------------------------------
// K2c: per-block exclusive scan + base -> cursor in d_cnt.
//      Also converts deg -> dinv (fused, after k_prep completed).
// ---------------------------------------------------------------------------
__global__ void k_scan3(int n) {
    __shared__ int wsum[SCAN_B / 32];
    int t = threadIdx.x;
    int lane = t & 31, w = t >> 5;
    int i = blockIdx.x * SCAN_B + t;
    int v = (i < n) ? d_cnt[i] : 0;
    int s = v;
#pragma unroll
    for (int off = 1; off < 32; off <<= 1) {
        int u = __shfl_up_sync(0xffffffffu, s, off);
        if (lane >= off) s += u;
    }
    if (lane == 31) wsum[w] = s;
    __syncthreads();
    if (t == 0) {
        int run = 0;
#pragma unroll
        for (int j = 0; j < SCAN_B / 32; j++) {
            int c = wsum[j]; wsum[j] = run; run += c;
        }
    }
    __syncthreads();
    if (i < n) {
        d_cnt[i] = (s - v) + wsum[w] + d_bsum[blockIdx.x];
        float dg = d_deg[i];
        d_deg[i] = (dg > 0.0f) ? rsqrtf(dg) : 0.0f;
    }
}

// ---------------------------------------------------------------------------
// K3: reorder edges into CSR-by-dst:  coef = -dinv[src] * w * dinv[dst]
// (d_deg already holds dinv.) After this, d_cnt[i] == inclusive prefix.
// ---------------------------------------------------------------------------
__global__ void k_reorder(int E) {
    int e = blockIdx.x * blockDim.x + threadIdx.x;
    if (e >= E) return;
    float w = d_w[e];
    if (w == 0.0f) return;
    int s = d_src[e];
    int d = d_dst[e];
    float c = -d_deg[s] * w * d_deg[d];
    int pos = atomicAdd(&d_cnt[d], 1);
    d_esrc[pos]  = s;
    d_ecoef[pos] = c;
}

// ---------------------------------------------------------------------------
// K4: fused gather (tx1 in registers) + gates + output.
// One warp handles 4 nodes; lane = output feature. Gather inner loop is
// unrolled x4 with zero-padded lanes (4 independent LDGs in flight).
// Gate matvecs use fma.rn.f32x2 (2 nodes per instruction).
// ---------------------------------------------------------------------------
__global__ void k_gather_gates(const float* __restrict__ x,
                               const float* __restrict__ Wx,
                               const float* __restrict__ bx,
                               const float* __restrict__ bh,
                               const float* __restrict__ wc,
                               const float* __restrict__ bgate,
                               const float* __restrict__ linw,
                               const float* __restrict__ linb,
                               float* __restrict__ out, int n) {
    __shared__ float sW[6][F * F];   // Wi0, Wi1, Wc0, Wc1, Wo0, Wo1
    __shared__ float sBi[F], sBc[F], sBo[F], sWc2[F], sLw[F];
    __shared__ float sLb;

    int tid = threadIdx.x;
    for (int i = tid; i < F * F; i += blockDim.x) {
        sW[0][i] = Wx[0 * F * F + i];   // gate i, k=0
        sW[1][i] = Wx[1 * F * F + i];   // gate i, k=1
        sW[2][i] = Wx[4 * F * F + i];   // gate c, k=0
        sW[3][i] = Wx[5 * F * F + i];   // gate c, k=1
        sW[4][i] = Wx[6 * F * F + i];   // gate o, k=0
        sW[5][i] = Wx[7 * F * F + i];   // gate o, k=1
    }
    if (tid < F) {
        sBi[tid]  = bx[0 * F + tid] + bh[0 * F + tid] + bgate[0 * F + tid];
        sBc[tid]  = bx[2 * F + tid] + bh[2 * F + tid] + bgate[2 * F + tid];
        sBo[tid]  = bx[3 * F + tid] + bh[3 * F + tid] + bgate[3 * F + tid];
        sWc2[tid] = wc[2 * F + tid];
        sLw[tid]  = linw[tid];
        if (tid == 0) sLb = linb[0];
    }
    __syncthreads();

    int warp = tid >> 5;
    int lane = tid & 31;
    int base = (blockIdx.x * (blockDim.x >> 5) + warp) * 4;
    if (base >= n) return;

    // -------- gather phase: tx1 for 4 nodes into registers --------
    float xr[4], tr[4];
#pragma unroll
    for (int i = 0; i < 4; i++) {
        int nd = base + i;
        float acc = 0.0f, xv = 0.0f;
        if (nd < n) {                       // warp-uniform condition
            xv = x[nd * F + lane];
            int st = nd ? d_cnt[nd - 1] : 0;
            int en = d_cnt[nd];
            for (int b0 = st; b0 < en; b0 += 32) {
                int j = b0 + lane;
                int   sj = 0;
                float cj = 0.0f;
                if (j < en) { sj = d_esrc[j]; cj = d_ecoef[j]; }
                int mm = (min(32, en - b0) + 3) & ~3;
                for (int k = 0; k < mm; k += 4) {
                    int   s0 = __shfl_sync(0xffffffffu, sj, k);
                    int   s1 = __shfl_sync(0xffffffffu, sj, k + 1);
                    int   s2 = __shfl_sync(0xffffffffu, sj, k + 2);
                    int   s3 = __shfl_sync(0xffffffffu, sj, k + 3);
                    float c0 = __shfl_sync(0xffffffffu, cj, k);
                    float c1 = __shfl_sync(0xffffffffu, cj, k + 1);
                    float c2 = __shfl_sync(0xffffffffu, cj, k + 2);
                    float c3 = __shfl_sync(0xffffffffu, cj, k + 3);
                    float v0 = __ldg(&x[s0 * F + lane]);
                    float v1 = __ldg(&x[s1 * F + lane]);
                    float v2 = __ldg(&x[s2 * F + lane]);
                    float v3 = __ldg(&x[s3 * F + lane]);
                    acc += c0 * v0 + c1 * v1 + c2 * v2 + c3 * v3;
                }
            }
        }
        xr[i] = xv;
        tr[i] = acc;
    }

    // -------- gate phase: packed f32x2, 2 nodes per instruction --------
    float bi = sBi[lane], bc = sBc[lane], bo = sBo[lane];
    unsigned long long ai01 = pk2(bi, bi), ai23 = pk2(bi, bi);
    unsigned long long ac01 = pk2(bc, bc), ac23 = pk2(bc, bc);
    unsigned long long ao01 = pk2(bo, bo), ao23 = pk2(bo, bo);

#pragma unroll
    for (int f = 0; f < F; f++) {
        float w0 = sW[0][f * F + lane];
        float w1 = sW[1][f * F + lane];
        float w2 = sW[2][f * F + lane];
        float w3 = sW[3][f * F + lane];
        float w4 = sW[4][f * F + lane];
        float w5 = sW[5][f * F + lane];
        float xf0 = __shfl_sync(0xffffffffu, xr[0], f);
        float xf1 = __shfl_sync(0xffffffffu, xr[1], f);
        float xf2 = __shfl_sync(0xffffffffu, xr[2], f);
        float xf3 = __shfl_sync(0xffffffffu, xr[3], f);
        float tf0 = __shfl_sync(0xffffffffu, tr[0], f);
        float tf1 = __shfl_sync(0xffffffffu, tr[1], f);
        float tf2 = __shfl_sync(0xffffffffu, tr[2], f);
        float tf3 = __shfl_sync(0xffffffffu, tr[3], f);
        unsigned long long x01 = pk2(xf0, xf1), x23 = pk2(xf2, xf3);
        unsigned long long t01 = pk2(tf0, tf1), t23 = pk2(tf2, tf3);
        unsigned long long W0 = pk2(w0, w0), W1 = pk2(w1, w1);
        unsigned long long W2 = pk2(w2, w2), W3 = pk2(w3, w3);
        unsigned long long W4 = pk2(w4, w4), W5 = pk2(w5, w5);
        ai01 = fma2(x01, W0, fma2(t01, W1, ai01));
        ai23 = fma2(x23, W0, fma2(t23, W1, ai23));
        ac01 = fma2(x01, W2, fma2(t01, W3, ac01));
        ac23 = fma2(x23, W2, fma2(t23, W3, ac23));
        ao01 = fma2(x01, W4, fma2(t01, W5, ao01));
        ao23 = fma2(x23, W4, fma2(t23, W5, ao23));
    }

    float ai[4], ac[4], ao[4];
    upk2(ai01, ai[0], ai[1]); upk2(ai23, ai[2], ai[3]);
    upk2(ac01, ac[0], ac[1]); upk2(ac23, ac[2], ac[3]);
    upk2(ao01, ao[0], ao[1]); upk2(ao23, ao[2], ao[3]);

    float wcl = sWc2[lane], lwl = sLw[lane], lb = sLb;
#pragma unroll
    for (int i = 0; i < 4; i++) {
        int nd = base + i;
        if (nd >= n) break;                  // warp-uniform
        float I = 1.0f / (1.0f + expf(-ai[i]));
        float T = tanhf(ac[i]);
        float C = I * T;
        float O = 1.0f / (1.0f + expf(-(ao[i] + wcl * C)));
        float H = O * tanhf(C);
        float r = fmaxf(H, 0.0f) * lwl;
#pragma unroll
        for (int off = 16; off > 0; off >>= 1)
            r += __shfl_xor_sync(0xffffffffu, r, off);
        if (lane == 0) out[nd] = r + lb;
    }
}

// ---------------------------------------------------------------------------
extern "C" void kernel_launch(void* const* d_in, const int* in_sizes, int n_in,
                              void* d_out, int out_size) {
    const float* x     = (const float*)d_in[0];
    const void*  ei    = d_in[1];
    const float* ew    = (const float*)d_in[2];
    const float* Wx    = (const float*)d_in[3];
    const float* bx    = (const float*)d_in[4];
    // d_in[5] = Wh (dead: H_prev == 0)
    const float* bh    = (const float*)d_in[6];
    const float* wc    = (const float*)d_in[7];
    const float* bgate = (const float*)d_in[8];
    const float* linw  = (const float*)d_in[9];
    const float* linb  = (const float*)d_in[10];
    float*       out   = (float*)d_out;

    const int N = in_sizes[0] / F;
    const int E = in_sizes[2];

    const int B  = 256;
    const int NB = (N + SCAN_B - 1) / SCAN_B;   // scan blocks (<=1024)

    k_init<<<(N + B - 1) / B, B>>>(ei, E, N);
    k_prep<<<(E + B - 1) / B, B>>>(ei, ew, E, N);
    k_scan1<<<NB, SCAN_B>>>(N);
    k_scan2<<<1, 1024>>>(NB);
    k_scan3<<<NB, SCAN_B>>>(N);
    k_reorder<<<(E + B - 1) / B, B>>>(E);
    // 8 warps/block, 4 nodes/warp -> 32 nodes per block
    k_gather_gates<<<(N + 31) / 32, B>>>(x, Wx, bx, bh, wc, bgate, linw, linb,
                                         out, N);
}

// round 14
// speedup vs baseline: 1.5534x; 1.0632x over previous
#include <cuda_runtime.h>
#include <cuda_bf16.h>
#include <math.h>

// Problem constants (fixed by the dataset)
#define MAXN 100000
#define MAXE 1600000
#define F 32            // F_IN == F_OUT == 32
#define SCAN_B 256      // elements per scan block

// Scratch (static device globals; no allocation allowed)
__device__ int   d_idx64;            // 1 if edge_index is int64, 0 if int32
__device__ float d_deg[MAXN];        // degree -> dinv (after k_scan3)
__device__ int   d_cnt[MAXN];        // counts -> exclusive prefix (cursor) -> inclusive
__device__ int   d_bsum[1024];       // per-block sums for the scan
__device__ int   d_src[MAXE];        // int32 source indices (unsorted)
__device__ int   d_dst[MAXE];        // int32 dest indices (unsorted)
__device__ float d_w[MAXE];          // weight, zeroed for self loops / bad edges
__device__ int2  d_edge[MAXE];       // CSR-by-dst: {src, coef bits} interleaved

// ---------------------------------------------------------------------------
// f32x2 packed-pipe helpers (sm_103a dual-fp32)
// ---------------------------------------------------------------------------
__device__ __forceinline__ unsigned long long pk2(float lo, float hi) {
    unsigned long long r;
    asm("mov.b64 %0, {%1, %2};" : "=l"(r) : "f"(lo), "f"(hi));
    return r;
}
__device__ __forceinline__ void upk2(unsigned long long v, float& lo, float& hi) {
    asm("mov.b64 {%0, %1}, %2;" : "=f"(lo), "=f"(hi) : "l"(v));
}
__device__ __forceinline__ unsigned long long fma2(unsigned long long a,
                                                   unsigned long long b,
                                                   unsigned long long c) {
    unsigned long long d;
    asm("fma.rn.f32x2 %0, %1, %2, %3;" : "=l"(d) : "l"(a), "l"(b), "l"(c));
    return d;
}

// ---------------------------------------------------------------------------
// K0: zero deg/cnt; block 0, warp 0 additionally detects edge_index dtype.
// ---------------------------------------------------------------------------
__global__ void k_init(const void* __restrict__ ei, int E, int n) {
    int i = blockIdx.x * blockDim.x + threadIdx.x;
    if (i < n) { d_deg[i] = 0.0f; d_cnt[i] = 0; }
    if (blockIdx.x == 0 && threadIdx.x < 32) {
        const long long* p = (const long long*)ei;
        int lane = threadIdx.x;
        long long a = p[lane];
        long long b = p[E + lane];
        int bad = (a < 0 || a >= n || b < 0 || b >= n) ? 1 : 0;
        unsigned m = __ballot_sync(0xffffffffu, bad);
        if (lane == 0) d_idx64 = (m == 0u) ? 1 : 0;
    }
}

// ---------------------------------------------------------------------------
// K1: single pass over edge_index:
//   - convert indices to int32 scratch
//   - zero self-loop / OOB weights
//   - deg[src] += w  and  cnt[dst] += 1 (skip dead edges entirely)
// ---------------------------------------------------------------------------
__global__ void k_prep(const void* __restrict__ ei,
                       const float* __restrict__ ew, int E, int n) {
    int e = blockIdx.x * blockDim.x + threadIdx.x;
    if (e >= E) return;
    int s, d;
    if (d_idx64) {
        const long long* p = (const long long*)ei;
        s = (int)p[e];
        d = (int)p[E + e];
    } else {
        const int* p = (const int*)ei;
        s = p[e];
        d = p[E + e];
    }
    float w = ew[e];
    if ((unsigned)s >= (unsigned)n || (unsigned)d >= (unsigned)n) {
        s = 0; d = 0; w = 0.0f;
    }
    if (s == d) w = 0.0f;
    d_src[e] = s;
    d_dst[e] = d;
    d_w[e]   = w;
    if (w != 0.0f) {
        atomicAdd(&d_deg[s], w);
        atomicAdd(&d_cnt[d], 1);
    }
}

// ---------------------------------------------------------------------------
// K2a: per-block sums of cnt (SCAN_B elements per block, coalesced)
// ---------------------------------------------------------------------------
__global__ void k_scan1(int n) {
    __shared__ int wsum[SCAN_B / 32];
    int t = threadIdx.x;
    int i = blockIdx.x * SCAN_B + t;
    int v = (i < n) ? d_cnt[i] : 0;
#pragma unroll
    for (int off = 16; off > 0; off >>= 1)
        v += __shfl_down_sync(0xffffffffu, v, off);
    if ((t & 31) == 0) wsum[t >> 5] = v;
    __syncthreads();
    if (t == 0) {
        int s = 0;
#pragma unroll
        for (int j = 0; j < SCAN_B / 32; j++) s += wsum[j];
        d_bsum[blockIdx.x] = s;
    }
}

// ---------------------------------------------------------------------------
// K2b: one block, exclusive scan of per-block sums (nb <= 1024).
// Warp shfl scan + one cross-warp step (2 barriers, not 20).
// ---------------------------------------------------------------------------
__global__ void k_scan2(int nb) {
    __shared__ int wtot[32];
    int t = threadIdx.x;
    int lane = t & 31, w = t >> 5;
    int v = (t < nb) ? d_bsum[t] : 0;
    int s = v;
#pragma unroll
    for (int off = 1; off < 32; off <<= 1) {
        int u = __shfl_up_sync(0xffffffffu, s, off);
        if (lane >= off) s += u;
    }
    if (lane == 31) wtot[w] = s;
    __syncthreads();
    if (w == 0) {
        int val = wtot[lane];
        int sc = val;
#pragma unroll
        for (int off = 1; off < 32; off <<= 1) {
            int u = __shfl_up_sync(0xffffffffu, sc, off);
            if (lane >= off) sc += u;
        }
        wtot[lane] = sc - val;       // exclusive base per warp
    }
    __syncthreads();
    if (t < nb) d_bsum[t] = (s - v) + wtot[w];   // exclusive prefix
}

// ---------------------------------------------------------------------------
// K2c: per-block exclusive scan + base -> cursor in d_cnt.
//      Also converts deg -> dinv (fused, after k_prep completed).
// ---------------------------------------------------------------------------
__global__ void k_scan3(int n) {
    __shared__ int wsum[SCAN_B / 32];
    int t = threadIdx.x;
    int lane = t & 31, w = t >> 5;
    int i = blockIdx.x * SCAN_B + t;
    int v = (i < n) ? d_cnt[i] : 0;
    int s = v;
#pragma unroll
    for (int off = 1; off < 32; off <<= 1) {
        int u = __shfl_up_sync(0xffffffffu, s, off);
        if (lane >= off) s += u;
    }
    if (lane == 31) wsum[w] = s;
    __syncthreads();
    if (t == 0) {
        int run = 0;
#pragma unroll
        for (int j = 0; j < SCAN_B / 32; j++) {
            int c = wsum[j]; wsum[j] = run; run += c;
        }
    }
    __syncthreads();
    if (i < n) {
        d_cnt[i] = (s - v) + wsum[w] + d_bsum[blockIdx.x];
        float dg = d_deg[i];
        d_deg[i] = (dg > 0.0f) ? rsqrtf(dg) : 0.0f;
    }
}

// ---------------------------------------------------------------------------
// K3: reorder edges into CSR-by-dst as int2 {src, coefbits} (one STG.64).
//     coef = -dinv[src] * w * dinv[dst]   (d_deg holds dinv)
// ---------------------------------------------------------------------------
__global__ void k_reorder(int E) {
    int e = blockIdx.x * blockDim.x + threadIdx.x;
    if (e >= E) return;
    float w = d_w[e];
    if (w == 0.0f) return;
    int s = d_src[e];
    int d = d_dst[e];
    float c = -d_deg[s] * w * d_deg[d];
    int pos = atomicAdd(&d_cnt[d], 1);
    d_edge[pos] = make_int2(s, __float_as_int(c));
}

// ---------------------------------------------------------------------------
// K4: fused gather (tx1 in registers) + gates + output.
// One warp handles 4 nodes; lane = output feature. Gather inner loop is
// unrolled x4 with zero-padded lanes (4 independent LDGs in flight);
// edge metadata is one LDG.64 per lane. Gate matvecs use fma.rn.f32x2.
// ---------------------------------------------------------------------------
__global__ void k_gather_gates(const float* __restrict__ x,
                               const float* __restrict__ Wx,
                               const float* __restrict__ bx,
                               const float* __restrict__ bh,
                               const float* __restrict__ wc,
                               const float* __restrict__ bgate,
                               const float* __restrict__ linw,
                               const float* __restrict__ linb,
                               float* __restrict__ out, int n) {
    __shared__ float sW[6][F * F];   // Wi0, Wi1, Wc0, Wc1, Wo0, Wo1
    __shared__ float sBi[F], sBc[F], sBo[F], sWc2[F], sLw[F];
    __shared__ float sLb;

    int tid = threadIdx.x;
    for (int i = tid; i < F * F; i += blockDim.x) {
        sW[0][i] = Wx[0 * F * F + i];   // gate i, k=0
        sW[1][i] = Wx[1 * F * F + i];   // gate i, k=1
        sW[2][i] = Wx[4 * F * F + i];   // gate c, k=0
        sW[3][i] = Wx[5 * F * F + i];   // gate c, k=1
        sW[4][i] = Wx[6 * F * F + i];   // gate o, k=0
        sW[5][i] = Wx[7 * F * F + i];   // gate o, k=1
    }
    if (tid < F) {
        sBi[tid]  = bx[0 * F + tid] + bh[0 * F + tid] + bgate[0 * F + tid];
        sBc[tid]  = bx[2 * F + tid] + bh[2 * F + tid] + bgate[2 * F + tid];
        sBo[tid]  = bx[3 * F + tid] + bh[3 * F + tid] + bgate[3 * F + tid];
        sWc2[tid] = wc[2 * F + tid];
        sLw[tid]  = linw[tid];
        if (tid == 0) sLb = linb[0];
    }
    __syncthreads();

    int warp = tid >> 5;
    int lane = tid & 31;
    int base = (blockIdx.x * (blockDim.x >> 5) + warp) * 4;
    if (base >= n) return;

    // -------- gather phase: tx1 for 4 nodes into registers --------
    float xr[4], tr[4];
#pragma unroll
    for (int i = 0; i < 4; i++) {
        int nd = base + i;
        float acc = 0.0f, xv = 0.0f;
        if (nd < n) {                       // warp-uniform condition
            xv = x[nd * F + lane];
            int st = nd ? d_cnt[nd - 1] : 0;
            int en = d_cnt[nd];
            for (int b0 = st; b0 < en; b0 += 32) {
                int j = b0 + lane;
                int   sj = 0;
                float cj = 0.0f;
                if (j < en) { int2 ed = d_edge[j]; sj = ed.x; cj = __int_as_float(ed.y); }
                int mm = (min(32, en - b0) + 3) & ~3;
                for (int k = 0; k < mm; k += 4) {
                    int   s0 = __shfl_sync(0xffffffffu, sj, k);
                    int   s1 = __shfl_sync(0xffffffffu, sj, k + 1);
                    int   s2 = __shfl_sync(0xffffffffu, sj, k + 2);
                    int   s3 = __shfl_sync(0xffffffffu, sj, k + 3);
                    float c0 = __shfl_sync(0xffffffffu, cj, k);
                    float c1 = __shfl_sync(0xffffffffu, cj, k + 1);
                    float c2 = __shfl_sync(0xffffffffu, cj, k + 2);
                    float c3 = __shfl_sync(0xffffffffu, cj, k + 3);
                    float v0 = __ldg(&x[s0 * F + lane]);
                    float v1 = __ldg(&x[s1 * F + lane]);
                    float v2 = __ldg(&x[s2 * F + lane]);
                    float v3 = __ldg(&x[s3 * F + lane]);
                    acc += c0 * v0 + c1 * v1 + c2 * v2 + c3 * v3;
                }
            }
        }
        xr[i] = xv;
        tr[i] = acc;
    }

    // -------- gate phase: packed f32x2, 2 nodes per instruction --------
    float bi = sBi[lane], bc = sBc[lane], bo = sBo[lane];
    unsigned long long ai01 = pk2(bi, bi), ai23 = pk2(bi, bi);
    unsigned long long ac01 = pk2(bc, bc), ac23 = pk2(bc, bc);
    unsigned long long ao01 = pk2(bo, bo), ao23 = pk2(bo, bo);

#pragma unroll
    for (int f = 0; f < F; f++) {
        float w0 = sW[0][f * F + lane];
        float w1 = sW[1][f * F + lane];
        float w2 = sW[2][f * F + lane];
        float w3 = sW[3][f * F + lane];
        float w4 = sW[4][f * F + lane];
        float w5 = sW[5][f * F + lane];
        float xf0 = __shfl_sync(0xffffffffu, xr[0], f);
        float xf1 = __shfl_sync(0xffffffffu, xr[1], f);
        float xf2 = __shfl_sync(0xffffffffu, xr[2], f);
        float xf3 = __shfl_sync(0xffffffffu, xr[3], f);
        float tf0 = __shfl_sync(0xffffffffu, tr[0], f);
        float tf1 = __shfl_sync(0xffffffffu, tr[1], f);
        float tf2 = __shfl_sync(0xffffffffu, tr[2], f);
        float tf3 = __shfl_sync(0xffffffffu, tr[3], f);
        unsigned long long x01 = pk2(xf0, xf1), x23 = pk2(xf2, xf3);
        unsigned long long t01 = pk2(tf0, tf1), t23 = pk2(tf2, tf3);
        unsigned long long W0 = pk2(w0, w0), W1 = pk2(w1, w1);
        unsigned long long W2 = pk2(w2, w2), W3 = pk2(w3, w3);
        unsigned long long W4 = pk2(w4, w4), W5 = pk2(w5, w5);
        ai01 = fma2(x01, W0, fma2(t01, W1, ai01));
        ai23 = fma2(x23, W0, fma2(t23, W1, ai23));
        ac01 = fma2(x01, W2, fma2(t01, W3, ac01));
        ac23 = fma2(x23, W2, fma2(t23, W3, ac23));
        ao01 = fma2(x01, W4, fma2(t01, W5, ao01));
        ao23 = fma2(x23, W4, fma2(t23, W5, ao23));
    }

    float ai[4], ac[4], ao[4];
    upk2(ai01, ai[0], ai[1]); upk2(ai23, ai[2], ai[3]);
    upk2(ac01, ac[0], ac[1]); upk2(ac23, ac[2], ac[3]);
    upk2(ao01, ao[0], ao[1]); upk2(ao23, ao[2], ao[3]);

    float wcl = sWc2[lane], lwl = sLw[lane], lb = sLb;
#pragma unroll
    for (int i = 0; i < 4; i++) {
        int nd = base + i;
        if (nd >= n) break;                  // warp-uniform
        float I = 1.0f / (1.0f + expf(-ai[i]));
        float T = tanhf(ac[i]);
        float C = I * T;
        float O = 1.0f / (1.0f + expf(-(ao[i] + wcl * C)));
        float H = O * tanhf(C);
        float r = fmaxf(H, 0.0f) * lwl;
#pragma unroll
        for (int off = 16; off > 0; off >>= 1)
            r += __shfl_xor_sync(0xffffffffu, r, off);
        if (lane == 0) out[nd] = r + lb;
    }
}

// ---------------------------------------------------------------------------
extern "C" void kernel_launch(void* const* d_in, const int* in_sizes, int n_in,
                              void* d_out, int out_size) {
    const float* x     = (const float*)d_in[0];
    const void*  ei    = d_in[1];
    const float* ew    = (const float*)d_in[2];
    const float* Wx    = (const float*)d_in[3];
    const float* bx    = (const float*)d_in[4];
    // d_in[5] = Wh (dead: H_prev == 0)
    const float* bh    = (const float*)d_in[6];
    const float* wc    = (const float*)d_in[7];
    const float* bgate = (const float*)d_in[8];
    const float* linw  = (const float*)d_in[9];
    const float* linb  = (const float*)d_in[10];
    float*       out   = (float*)d_out;

    const int N = in_sizes[0] / F;
    const int E = in_sizes[2];

    const int B  = 256;
    const int NB = (N + SCAN_B - 1) / SCAN_B;   // scan blocks (<=1024)

    k_init<<<(N + B - 1) / B, B>>>(ei, E, N);
    k_prep<<<(E + B - 1) / B, B>>>(ei, ew, E, N);
    k_scan1<<<NB, SCAN_B>>>(N);
    k_scan2<<<1, 1024>>>(NB);
    k_scan3<<<NB, SCAN_B>>>(N);
    k_reorder<<<(E + B - 1) / B, B>>>(E);
    // 8 warps/block, 4 nodes/warp -> 32 nodes per block
    k_gather_gates<<<(N + 31) / 32, B>>>(x, Wx, bx, bh, wc, bgate, linw, linb,
                                         out, N);
}

// round 15
// speedup vs baseline: 1.5537x; 1.0002x over previous
#include <cuda_runtime.h>
#include <cuda_bf16.h>
#include <math.h>

// Problem constants (fixed by the dataset)
#define MAXN 100000
#define MAXE 1600000
#define F 32            // F_IN == F_OUT == 32
#define SCAN_B 256      // elements per scan block

// Scratch (static device globals; no allocation allowed)
__device__ int   d_idx64;            // 1 if edge_index is int64, 0 if int32
__device__ float d_deg[MAXN];        // degree -> dinv (after k_scan23)
__device__ int   d_cnt[MAXN];        // counts -> cursor -> inclusive prefix
__device__ int   d_bsum[1024];       // per-block aggregate sums for the scan
__device__ int2  d_edge[MAXE];       // CSR-by-dst: {src, coef bits} interleaved

// ---------------------------------------------------------------------------
// f32x2 packed-pipe helpers (sm_103a dual-fp32)
// ---------------------------------------------------------------------------
__device__ __forceinline__ unsigned long long pk2(float lo, float hi) {
    unsigned long long r;
    asm("mov.b64 %0, {%1, %2};" : "=l"(r) : "f"(lo), "f"(hi));
    return r;
}
__device__ __forceinline__ void upk2(unsigned long long v, float& lo, float& hi) {
    asm("mov.b64 {%0, %1}, %2;" : "=f"(lo), "=f"(hi) : "l"(v));
}
__device__ __forceinline__ unsigned long long fma2(unsigned long long a,
                                                   unsigned long long b,
                                                   unsigned long long c) {
    unsigned long long d;
    asm("fma.rn.f32x2 %0, %1, %2, %3;" : "=l"(d) : "l"(a), "l"(b), "l"(c));
    return d;
}

// ---------------------------------------------------------------------------
// Shared edge decode (dtype-dispatched on d_idx64)
// ---------------------------------------------------------------------------
__device__ __forceinline__ void decode_edge(const void* __restrict__ ei,
                                            const float* __restrict__ ew,
                                            int E, int n, int e,
                                            int& s, int& d, float& w) {
    if (d_idx64) {
        const long long* p = (const long long*)ei;
        s = (int)p[e];
        d = (int)p[E + e];
    } else {
        const int* p = (const int*)ei;
        s = p[e];
        d = p[E + e];
    }
    w = ew[e];
    if ((unsigned)s >= (unsigned)n || (unsigned)d >= (unsigned)n) {
        s = 0; d = 0; w = 0.0f;
    }
    if (s == d) w = 0.0f;
}

// ---------------------------------------------------------------------------
// K0: zero deg/cnt; block 0, warp 0 additionally detects edge_index dtype.
// ---------------------------------------------------------------------------
__global__ void k_init(const void* __restrict__ ei, int E, int n) {
    int i = blockIdx.x * blockDim.x + threadIdx.x;
    if (i < n) { d_deg[i] = 0.0f; d_cnt[i] = 0; }
    if (blockIdx.x == 0 && threadIdx.x < 32) {
        const long long* p = (const long long*)ei;
        int lane = threadIdx.x;
        long long a = p[lane];
        long long b = p[E + lane];
        int bad = (a < 0 || a >= n || b < 0 || b >= n) ? 1 : 0;
        unsigned m = __ballot_sync(0xffffffffu, bad);
        if (lane == 0) d_idx64 = (m == 0u) ? 1 : 0;
    }
}

// ---------------------------------------------------------------------------
// K1: count pass (no staging writes):
//   deg[src] += w  and  cnt[dst] += 1 for live edges
// ---------------------------------------------------------------------------
__global__ void k_prep(const void* __restrict__ ei,
                       const float* __restrict__ ew, int E, int n) {
    int e = blockIdx.x * blockDim.x + threadIdx.x;
    if (e >= E) return;
    int s, d; float w;
    decode_edge(ei, ew, E, n, e, s, d, w);
    if (w != 0.0f) {
        atomicAdd(&d_deg[s], w);
        atomicAdd(&d_cnt[d], 1);
    }
}

// ---------------------------------------------------------------------------
// K2a: per-block aggregate sums of cnt (SCAN_B elements per block)
// ---------------------------------------------------------------------------
__global__ void k_scan1(int n) {
    __shared__ int wsum[SCAN_B / 32];
    int t = threadIdx.x;
    int i = blockIdx.x * SCAN_B + t;
    int v = (i < n) ? d_cnt[i] : 0;
#pragma unroll
    for (int off = 16; off > 0; off >>= 1)
        v += __shfl_down_sync(0xffffffffu, v, off);
    if ((t & 31) == 0) wsum[t >> 5] = v;
    __syncthreads();
    if (t == 0) {
        int s = 0;
#pragma unroll
        for (int j = 0; j < SCAN_B / 32; j++) s += wsum[j];
        d_bsum[blockIdx.x] = s;
    }
}

// ---------------------------------------------------------------------------
// K2b: per-block exclusive scan -> cursor in d_cnt.  Each block computes its
// own base by summing all preceding block aggregates (parallel redundant
// reduction; <=2 coalesced chunks per thread).  Also deg -> dinv (fused).
// ---------------------------------------------------------------------------
__global__ void k_scan23(int n) {
    __shared__ int wsum[SCAN_B / 32];
    __shared__ int sred[SCAN_B / 32];
    __shared__ int sbase;
    int t = threadIdx.x;
    int lane = t & 31, w = t >> 5;

    // ---- base = sum of d_bsum[0 .. blockIdx.x) ----
    int pre = 0;
    for (int c = t; c < blockIdx.x; c += SCAN_B) pre += d_bsum[c];
#pragma unroll
    for (int off = 16; off > 0; off >>= 1)
        pre += __shfl_down_sync(0xffffffffu, pre, off);
    if (lane == 0) sred[w] = pre;
    __syncthreads();
    if (t == 0) {
        int b = 0;
#pragma unroll
        for (int j = 0; j < SCAN_B / 32; j++) b += sred[j];
        sbase = b;
    }
    __syncthreads();

    // ---- local exclusive scan of this block's SCAN_B counts ----
    int i = blockIdx.x * SCAN_B + t;
    int v = (i < n) ? d_cnt[i] : 0;
    int s = v;
#pragma unroll
    for (int off = 1; off < 32; off <<= 1) {
        int u = __shfl_up_sync(0xffffffffu, s, off);
        if (lane >= off) s += u;
    }
    if (lane == 31) wsum[w] = s;
    __syncthreads();
    if (t == 0) {
        int run = 0;
#pragma unroll
        for (int j = 0; j < SCAN_B / 32; j++) {
            int c = wsum[j]; wsum[j] = run; run += c;
        }
    }
    __syncthreads();
    if (i < n) {
        d_cnt[i] = (s - v) + wsum[w] + sbase;
        float dg = d_deg[i];
        d_deg[i] = (dg > 0.0f) ? rsqrtf(dg) : 0.0f;
    }
}

// ---------------------------------------------------------------------------
// K3: reorder edges into CSR-by-dst as int2 {src, coefbits} (one STG.64).
//     Re-decodes edge_index directly (no staging arrays).
//     coef = -dinv[src] * w * dinv[dst]   (d_deg holds dinv)
// ---------------------------------------------------------------------------
__global__ void k_reorder(const void* __restrict__ ei,
                          const float* __restrict__ ew, int E, int n) {
    int e = blockIdx.x * blockDim.x + threadIdx.x;
    if (e >= E) return;
    int s, d; float w;
    decode_edge(ei, ew, E, n, e, s, d, w);
    if (w == 0.0f) return;
    float c = -d_deg[s] * w * d_deg[d];
    int pos = atomicAdd(&d_cnt[d], 1);
    d_edge[pos] = make_int2(s, __float_as_int(c));
}

// ---------------------------------------------------------------------------
// K4: fused gather (tx1 in registers) + gates + output.
// One warp handles 4 nodes; lane = output feature. Gather inner loop is
// unrolled x4 with zero-padded lanes (4 independent LDGs in flight);
// edge metadata is one LDG.64 per lane. Gate matvecs use fma.rn.f32x2.
// ---------------------------------------------------------------------------
__global__ void k_gather_gates(const float* __restrict__ x,
                               const float* __restrict__ Wx,
                               const float* __restrict__ bx,
                               const float* __restrict__ bh,
                               const float* __restrict__ wc,
                               const float* __restrict__ bgate,
                               const float* __restrict__ linw,
                               const float* __restrict__ linb,
                               float* __restrict__ out, int n) {
    __shared__ float sW[6][F * F];   // Wi0, Wi1, Wc0, Wc1, Wo0, Wo1
    __shared__ float sBi[F], sBc[F], sBo[F], sWc2[F], sLw[F];
    __shared__ float sLb;

    int tid = threadIdx.x;
    for (int i = tid; i < F * F; i += blockDim.x) {
        sW[0][i] = Wx[0 * F * F + i];   // gate i, k=0
        sW[1][i] = Wx[1 * F * F + i];   // gate i, k=1
        sW[2][i] = Wx[4 * F * F + i];   // gate c, k=0
        sW[3][i] = Wx[5 * F * F + i];   // gate c, k=1
        sW[4][i] = Wx[6 * F * F + i];   // gate o, k=0
        sW[5][i] = Wx[7 * F * F + i];   // gate o, k=1
    }
    if (tid < F) {
        sBi[tid]  = bx[0 * F + tid] + bh[0 * F + tid] + bgate[0 * F + tid];
        sBc[tid]  = bx[2 * F + tid] + bh[2 * F + tid] + bgate[2 * F + tid];
        sBo[tid]  = bx[3 * F + tid] + bh[3 * F + tid] + bgate[3 * F + tid];
        sWc2[tid] = wc[2 * F + tid];
        sLw[tid]  = linw[tid];
        if (tid == 0) sLb = linb[0];
    }
    __syncthreads();

    int warp = tid >> 5;
    int lane = tid & 31;
    int base = (blockIdx.x * (blockDim.x >> 5) + warp) * 4;
    if (base >= n) return;

    // -------- gather phase: tx1 for 4 nodes into registers --------
    float xr[4], tr[4];
#pragma unroll
    for (int i = 0; i < 4; i++) {
        int nd = base + i;
        float acc = 0.0f, xv = 0.0f;
        if (nd < n) {                       // warp-uniform condition
            xv = x[nd * F + lane];
            int st = nd ? d_cnt[nd - 1] : 0;
            int en = d_cnt[nd];
            for (int b0 = st; b0 < en; b0 += 32) {
                int j = b0 + lane;
                int   sj = 0;
                float cj = 0.0f;
                if (j < en) { int2 ed = d_edge[j]; sj = ed.x; cj = __int_as_float(ed.y); }
                int mm = (min(32, en - b0) + 3) & ~3;
                for (int k = 0; k < mm; k += 4) {
                    int   s0 = __shfl_sync(0xffffffffu, sj, k);
                    int   s1 = __shfl_sync(0xffffffffu, sj, k + 1);
                    int   s2 = __shfl_sync(0xffffffffu, sj, k + 2);
                    int   s3 = __shfl_sync(0xffffffffu, sj, k + 3);
                    float c0 = __shfl_sync(0xffffffffu, cj, k);
                    float c1 = __shfl_sync(0xffffffffu, cj, k + 1);
                    float c2 = __shfl_sync(0xffffffffu, cj, k + 2);
                    float c3 = __shfl_sync(0xffffffffu, cj, k + 3);
                    float v0 = __ldg(&x[s0 * F + lane]);
                    float v1 = __ldg(&x[s1 * F + lane]);
                    float v2 = __ldg(&x[s2 * F + lane]);
                    float v3 = __ldg(&x[s3 * F + lane]);
                    acc += c0 * v0 + c1 * v1 + c2 * v2 + c3 * v3;
                }
            }
        }
        xr[i] = xv;
        tr[i] = acc;
    }

    // -------- gate phase: packed f32x2, 2 nodes per instruction --------
    float bi = sBi[lane], bc = sBc[lane], bo = sBo[lane];
    unsigned long long ai01 = pk2(bi, bi), ai23 = pk2(bi, bi);
    unsigned long long ac01 = pk2(bc, bc), ac23 = pk2(bc, bc);
    unsigned long long ao01 = pk2(bo, bo), ao23 = pk2(bo, bo);

#pragma unroll
    for (int f = 0; f < F; f++) {
        float w0 = sW[0][f * F + lane];
        float w1 = sW[1][f * F + lane];
        float w2 = sW[2][f * F + lane];
        float w3 = sW[3][f * F + lane];
        float w4 = sW[4][f * F + lane];
        float w5 = sW[5][f * F + lane];
        float xf0 = __shfl_sync(0xffffffffu, xr[0], f);
        float xf1 = __shfl_sync(0xffffffffu, xr[1], f);
        float xf2 = __shfl_sync(0xffffffffu, xr[2], f);
        float xf3 = __shfl_sync(0xffffffffu, xr[3], f);
        float tf0 = __shfl_sync(0xffffffffu, tr[0], f);
        float tf1 = __shfl_sync(0xffffffffu, tr[1], f);
        float tf2 = __shfl_sync(0xffffffffu, tr[2], f);
        float tf3 = __shfl_sync(0xffffffffu, tr[3], f);
        unsigned long long x01 = pk2(xf0, xf1), x23 = pk2(xf2, xf3);
        unsigned long long t01 = pk2(tf0, tf1), t23 = pk2(tf2, tf3);
        unsigned long long W0 = pk2(w0, w0), W1 = pk2(w1, w1);
        unsigned long long W2 = pk2(w2, w2), W3 = pk2(w3, w3);
        unsigned long long W4 = pk2(w4, w4), W5 = pk2(w5, w5);
        ai01 = fma2(x01, W0, fma2(t01, W1, ai01));
        ai23 = fma2(x23, W0, fma2(t23, W1, ai23));
        ac01 = fma2(x01, W2, fma2(t01, W3, ac01));
        ac23 = fma2(x23, W2, fma2(t23, W3, ac23));
        ao01 = fma2(x01, W4, fma2(t01, W5, ao01));
        ao23 = fma2(x23, W4, fma2(t23, W5, ao23));
    }

    float ai[4], ac[4], ao[4];
    upk2(ai01, ai[0], ai[1]); upk2(ai23, ai[2], ai[3]);
    upk2(ac01, ac[0], ac[1]); upk2(ac23, ac[2], ac[3]);
    upk2(ao01, ao[0], ao[1]); upk2(ao23, ao[2], ao[3]);

    float wcl = sWc2[lane], lwl = sLw[lane], lb = sLb;
#pragma unroll
    for (int i = 0; i < 4; i++) {
        int nd = base + i;
        if (nd >= n) break;                  // warp-uniform
        float I = 1.0f / (1.0f + expf(-ai[i]));
        float T = tanhf(ac[i]);
        float C = I * T;
        float O = 1.0f / (1.0f + expf(-(ao[i] + wcl * C)));
        float H = O * tanhf(C);
        float r = fmaxf(H, 0.0f) * lwl;
#pragma unroll
        for (int off = 16; off > 0; off >>= 1)
            r += __shfl_xor_sync(0xffffffffu, r, off);
        if (lane == 0) out[nd] = r + lb;
    }
}

// ---------------------------------------------------------------------------
extern "C" void kernel_launch(void* const* d_in, const int* in_sizes, int n_in,
                              void* d_out, int out_size) {
    const float* x     = (const float*)d_in[0];
    const void*  ei    = d_in[1];
    const float* ew    = (const float*)d_in[2];
    const float* Wx    = (const float*)d_in[3];
    const float* bx    = (const float*)d_in[4];
    // d_in[5] = Wh (dead: H_prev == 0)
    const float* bh    = (const float*)d_in[6];
    const float* wc    = (const float*)d_in[7];
    const float* bgate = (const float*)d_in[8];
    const float* linw  = (const float*)d_in[9];
    const float* linb  = (const float*)d_in[10];
    float*       out   = (float*)d_out;

    const int N = in_sizes[0] / F;
    const int E = in_sizes[2];

    const int B  = 256;
    const int NB = (N + SCAN_B - 1) / SCAN_B;   // scan blocks (<=1024)

    k_init<<<(N + B - 1) / B, B>>>(ei, E, N);
    k_prep<<<(E + B - 1) / B, B>>>(ei, ew, E, N);
    k_scan1<<<NB, SCAN_B>>>(N);
    k_scan23<<<NB, SCAN_B>>>(N);
    k_reorder<<<(E + B - 1) / B, B>>>(ei, ew, E, N);
    // 8 warps/block, 4 nodes/warp -> 32 nodes per block
    k_gather_gates<<<(N + 31) / 32, B>>>(x, Wx, bx, bh, wc, bgate, linw, linb,
                                         out, N);
}